// round 9
// baseline (speedup 1.0000x reference)
#include <cuda_runtime.h>
#include <cuda_bf16.h>

// FrozenBNBStableEmbedding fused gather+dequant+LayerNorm.
// R9: R5 warp-per-token structure, plus:
//  - scale folded into mean/rstd algebra (kills 64 FMUL/token)
//  - 4-way split accumulators (no deep FADD chain)
//  - cross-token software pipelining: next token's 8 weight loads issued
//    before the current token's butterfly reduction + epilogue
// (redux.sync.add.f32 does NOT exist on sm_103 — butterfly stays.)

#define D    1024
#define REP  16          // code-table replication
#define TPW  2           // tokens per warp
#define EPS  1e-5f

__global__ __launch_bounds__(256) void emb_ln_kernel(
    const int*   __restrict__ x,
    const int*   __restrict__ w,
    const float* __restrict__ absmax,
    const float* __restrict__ code,
    const float* __restrict__ lnw,
    const float* __restrict__ lnb,
    float*       __restrict__ out,
    int n_tokens)
{
    __shared__ float  s_code[256 * REP];  // s_code[idx*REP + slot]
    __shared__ float4 s_lnw[256];
    __shared__ float4 s_lnb[256];

    const int tid  = threadIdx.x;
    const int warp = tid >> 5;
    const int lane = tid & 31;

    // Fill replicated code table + LN params (once per CTA)
    {
        const float c = code[tid];
        float4 cv = make_float4(c, c, c, c);
        float4* dst = reinterpret_cast<float4*>(&s_code[tid * REP]);
        dst[0] = cv; dst[1] = cv; dst[2] = cv; dst[3] = cv;
        s_lnw[tid] = __ldg(&reinterpret_cast<const float4*>(lnw)[tid]);
        s_lnb[tid] = __ldg(&reinterpret_cast<const float4*>(lnb)[tid]);
    }
    __syncthreads();

    const float* tab = &s_code[lane & (REP - 1)];
    const int warp_g = blockIdx.x * 8 + warp;
    const int tok0   = warp_g * TPW;

    // Prime: token 0 loads
    float scale = __ldg(&absmax[__ldg(&x[tok0]) >> 2]);
    int4 q[8];
    {
        const int4* wrow = reinterpret_cast<const int4*>(
            w + (long long)__ldg(&x[tok0]) * D);
        #pragma unroll
        for (int i = 0; i < 8; ++i)
            q[i] = __ldg(&wrow[i * 32 + lane]);
    }

    #pragma unroll
    for (int t = 0; t < TPW; ++t) {
        const int tok = tok0 + t;

        // Dequant lookups (raw code values; scale folded out)
        float v[32];
        float sum0 = 0.f, sum1 = 0.f, sum2 = 0.f, sum3 = 0.f;
        float sq0 = 0.f, sq1 = 0.f, sq2 = 0.f, sq3 = 0.f;
        #pragma unroll
        for (int i = 0; i < 8; ++i) {
            float a = tab[(q[i].x & 255) * REP];
            float b = tab[(q[i].y & 255) * REP];
            float c = tab[(q[i].z & 255) * REP];
            float d = tab[(q[i].w & 255) * REP];
            v[i*4+0] = a; v[i*4+1] = b; v[i*4+2] = c; v[i*4+3] = d;
            sum0 += a; sum1 += b; sum2 += c; sum3 += d;
            sq0 += a*a; sq1 += b*b; sq2 += c*c; sq3 += d*d;
        }
        float sum = (sum0 + sum1) + (sum2 + sum3);
        float sq  = (sq0 + sq1) + (sq2 + sq3);

        // Prefetch next token's weights BEFORE the reduction so the
        // butterfly+epilogue (~400cyc) overlaps their memory latency.
        int4  qn[8];
        float scn = 0.0f;
        if (t + 1 < TPW) {
            const int rn = __ldg(&x[tok + 1]);
            scn = __ldg(&absmax[rn >> 2]);
            const int4* wrn = reinterpret_cast<const int4*>(w + (long long)rn * D);
            #pragma unroll
            for (int i = 0; i < 8; ++i)
                qn[i] = __ldg(&wrn[i * 32 + lane]);
        }

        // Butterfly reduction (sum & sq chains interleave)
        #pragma unroll
        for (int off = 16; off > 0; off >>= 1) {
            sum += __shfl_xor_sync(0xFFFFFFFFu, sum, off);
            sq  += __shfl_xor_sync(0xFFFFFFFFu, sq,  off);
        }

        // Stats in raw-code domain; scale enters only here
        const float mean_c = sum * (1.0f / D);
        const float var_c  = sq * (1.0f / D) - mean_c * mean_c;
        const float tscale = scale * rsqrtf(scale * scale * var_c + EPS);

        float4* orow = reinterpret_cast<float4*>(out) + (long long)tok * (D / 4);
        #pragma unroll
        for (int i = 0; i < 8; ++i) {
            const float4 gw = s_lnw[i * 32 + lane];
            const float4 gb = s_lnb[i * 32 + lane];
            float4 o;
            o.x = (v[i*4+0] - mean_c) * tscale * gw.x + gb.x;
            o.y = (v[i*4+1] - mean_c) * tscale * gw.y + gb.y;
            o.z = (v[i*4+2] - mean_c) * tscale * gw.z + gb.z;
            o.w = (v[i*4+3] - mean_c) * tscale * gw.w + gb.w;
            __stcs(&orow[i * 32 + lane], o);
        }

        #pragma unroll
        for (int i = 0; i < 8; ++i) q[i] = qn[i];
        scale = scn;
    }
}

extern "C" void kernel_launch(void* const* d_in, const int* in_sizes, int n_in,
                              void* d_out, int out_size)
{
    const int*   x      = (const int*)d_in[0];
    const int*   w      = (const int*)d_in[1];
    const float* absmax = (const float*)d_in[2];
    const float* code   = (const float*)d_in[3];
    const float* lnw    = (const float*)d_in[4];
    const float* lnb    = (const float*)d_in[5];
    float*       out    = (float*)d_out;

    const int n_tokens = in_sizes[0];                     // 16384
    const int tokens_per_cta = 8 * TPW;                   // 16
    const int grid = (n_tokens + tokens_per_cta - 1) / tokens_per_cta;  // 1024
    emb_ln_kernel<<<grid, 256>>>(x, w, absmax, code, lnw, lnb, out, n_tokens);
}